// round 17
// baseline (speedup 1.0000x reference)
#include <cuda_runtime.h>
#include <math_constants.h>
#include <cstdint>

// Problem constants
constexpr int B_ = 2;
constexpr int N_ = 2048;
constexpr int C_ = 1024;
constexpr int H_ = 16;
constexpr int D_ = 64;
constexpr int M_ = B_ * N_;      // 4096 rows of x
constexpr float SCALE = 0.125f;  // D^-0.5

// Scratch (device globals; no allocation allowed)
__device__ float g_q[(size_t)B_ * H_ * N_ * D_];   // [B*H, N, D]
__device__ float g_k[(size_t)B_ * H_ * N_ * D_];
__device__ float g_v[(size_t)B_ * H_ * N_ * D_];
__device__ float g_ao[(size_t)B_ * N_ * C_];       // attention output, [B*N, C]

// ---------------------------------------------------------------------------
// helpers
// ---------------------------------------------------------------------------
__device__ __forceinline__ unsigned f2tf(float f) {
    unsigned u;
    asm("cvt.rna.tf32.f32 %0, %1;" : "=r"(u) : "f"(f));
    return u;
}

__device__ __forceinline__ void mma_tf32(
    float& c0, float& c1, float& c2, float& c3,
    unsigned a0, unsigned a1, unsigned a2, unsigned a3,
    unsigned b0, unsigned b1)
{
    asm volatile(
        "mma.sync.aligned.m16n8k8.row.col.f32.tf32.tf32.f32 "
        "{%0,%1,%2,%3}, {%4,%5,%6,%7}, {%8,%9}, {%0,%1,%2,%3};"
        : "+f"(c0), "+f"(c1), "+f"(c2), "+f"(c3)
        : "r"(a0), "r"(a1), "r"(a2), "r"(a3), "r"(b0), "r"(b1));
}

// ---------------------------------------------------------------------------
// tf32 TN GEMM — EXACT R4/689.6us version: LDG->f2tf->STS double-buffered,
// stride-20 padded smem, conflict-free fragment loads.
// EPI=0: qkv + RoPE scatter.  EPI=1: bias add -> out.
// ---------------------------------------------------------------------------
constexpr int SA = 20;

template<int EPI>
__global__ __launch_bounds__(256) void gemm_tf32_kernel(
    const float* __restrict__ Ain, const float* __restrict__ W,
    const float* __restrict__ fcos, const float* __restrict__ fsin,
    const float* __restrict__ bias, float* __restrict__ out)
{
    __shared__ unsigned As[2][128 * SA];
    __shared__ unsigned Bs[2][128 * SA];

    const float* A = (EPI == 1) ? g_ao : Ain;

    const int tid = threadIdx.x;
    const int w = tid >> 5;
    const int lane = tid & 31;
    const int g = lane >> 2;
    const int t = lane & 3;
    const int wm = w >> 2;
    const int wn = w & 3;

    const int m0 = blockIdx.y * 128;
    const int n0 = blockIdx.x * 128;

    const int r0 = tid >> 2;
    const int c4 = (tid & 3) * 4;

    const float* ap0 = A + (size_t)(m0 + r0) * 1024 + c4;
    const float* ap1 = ap0 + (size_t)64 * 1024;
    const float* bp0 = W + (size_t)(n0 + r0) * 1024 + c4;
    const float* bp1 = bp0 + (size_t)64 * 1024;

    float acc[4][4][4];
#pragma unroll
    for (int i = 0; i < 4; i++)
#pragma unroll
        for (int j = 0; j < 4; j++)
#pragma unroll
            for (int q = 0; q < 4; q++) acc[i][j][q] = 0.f;

    float4 va0 = *(const float4*)(ap0);
    float4 va1 = *(const float4*)(ap1);
    float4 vb0 = *(const float4*)(bp0);
    float4 vb1 = *(const float4*)(bp1);
    {
        uint4 u;
        u.x = f2tf(va0.x); u.y = f2tf(va0.y); u.z = f2tf(va0.z); u.w = f2tf(va0.w);
        *(uint4*)&As[0][r0 * SA + c4] = u;
        u.x = f2tf(va1.x); u.y = f2tf(va1.y); u.z = f2tf(va1.z); u.w = f2tf(va1.w);
        *(uint4*)&As[0][(r0 + 64) * SA + c4] = u;
        u.x = f2tf(vb0.x); u.y = f2tf(vb0.y); u.z = f2tf(vb0.z); u.w = f2tf(vb0.w);
        *(uint4*)&Bs[0][r0 * SA + c4] = u;
        u.x = f2tf(vb1.x); u.y = f2tf(vb1.y); u.z = f2tf(vb1.z); u.w = f2tf(vb1.w);
        *(uint4*)&Bs[0][(r0 + 64) * SA + c4] = u;
    }
    __syncthreads();

    for (int kt = 0; kt < 64; kt++) {
        const int buf = kt & 1;
        if (kt < 63) {
            const int k0 = (kt + 1) * 16;
            va0 = *(const float4*)(ap0 + k0);
            va1 = *(const float4*)(ap1 + k0);
            vb0 = *(const float4*)(bp0 + k0);
            vb1 = *(const float4*)(bp1 + k0);
        }

#pragma unroll
        for (int ks = 0; ks < 2; ks++) {
            unsigned afr[4][4];
#pragma unroll
            for (int i = 0; i < 4; i++) {
                const unsigned* p =
                    &As[buf][(wm * 64 + i * 16 + g) * SA + ks * 8 + t];
                afr[i][0] = p[0];
                afr[i][1] = p[8 * SA];
                afr[i][2] = p[4];
                afr[i][3] = p[8 * SA + 4];
            }
            unsigned bfr[4][2];
#pragma unroll
            for (int j = 0; j < 4; j++) {
                const unsigned* p =
                    &Bs[buf][(wn * 32 + j * 8 + g) * SA + ks * 8 + t];
                bfr[j][0] = p[0];
                bfr[j][1] = p[4];
            }
#pragma unroll
            for (int i = 0; i < 4; i++)
#pragma unroll
                for (int j = 0; j < 4; j++)
                    mma_tf32(acc[i][j][0], acc[i][j][1], acc[i][j][2], acc[i][j][3],
                             afr[i][0], afr[i][1], afr[i][2], afr[i][3],
                             bfr[j][0], bfr[j][1]);
        }

        if (kt < 63) {
            const int nb = buf ^ 1;
            uint4 u;
            u.x = f2tf(va0.x); u.y = f2tf(va0.y); u.z = f2tf(va0.z); u.w = f2tf(va0.w);
            *(uint4*)&As[nb][r0 * SA + c4] = u;
            u.x = f2tf(va1.x); u.y = f2tf(va1.y); u.z = f2tf(va1.z); u.w = f2tf(va1.w);
            *(uint4*)&As[nb][(r0 + 64) * SA + c4] = u;
            u.x = f2tf(vb0.x); u.y = f2tf(vb0.y); u.z = f2tf(vb0.z); u.w = f2tf(vb0.w);
            *(uint4*)&Bs[nb][r0 * SA + c4] = u;
            u.x = f2tf(vb1.x); u.y = f2tf(vb1.y); u.z = f2tf(vb1.z); u.w = f2tf(vb1.w);
            *(uint4*)&Bs[nb][(r0 + 64) * SA + c4] = u;
            __syncthreads();
        }
    }

#pragma unroll
    for (int i = 0; i < 4; i++) {
        const int mlo = m0 + wm * 64 + i * 16 + g;
#pragma unroll
        for (int j = 0; j < 4; j++) {
            const int col = n0 + wn * 32 + j * 8 + 2 * t;
            if (EPI == 1) {
                const float2 bb = *(const float2*)&bias[col];
                float2 o0 = {acc[i][j][0] + bb.x, acc[i][j][1] + bb.y};
                float2 o1 = {acc[i][j][2] + bb.x, acc[i][j][3] + bb.y};
                *(float2*)&out[(size_t)mlo * 1024 + col] = o0;
                *(float2*)&out[(size_t)(mlo + 8) * 1024 + col] = o1;
            } else {
                const int part = col >> 10;
                const int h = (col >> 6) & (H_ - 1);
                const int d = col & (D_ - 1);
                const int f = d >> 1;
#pragma unroll
                for (int rr = 0; rr < 2; rr++) {
                    const int m = mlo + rr * 8;
                    const int b = m >> 11;
                    const int nr = m & (N_ - 1);
                    const float v0 = acc[i][j][rr * 2 + 0];
                    const float v1 = acc[i][j][rr * 2 + 1];
                    const size_t off =
                        (((size_t)(b * H_ + h) * N_) + nr) * D_ + d;
                    if (part == 2) {
                        float2 o = {v0, v1};
                        *(float2*)&g_v[off] = o;
                    } else {
                        const float c = fcos[nr * 32 + f];
                        const float s = fsin[nr * 32 + f];
                        float2 o = {v0 * c - v1 * s, v0 * s + v1 * c};
                        float* dst = (part == 0) ? g_q : g_k;
                        *(float2*)&dst[off] = o;
                    }
                }
            }
        }
    }
}

// ---------------------------------------------------------------------------
// Flash attention — R4-identical layouts & math (stride-68 affine, 64-key
// tiles), with RESCHEDULED staging only:
//   syncA -> STS V[it] (regs loaded LAST iter) -> LDG kv=K[it+1], vv=V[it+1]
//   -> S-GEMM(Ks=K[it]) -> softmax -> syncB -> STS K[it+1] -> O-GEMM(Vt).
// All load latency covered by a full tile of compute; 2 syncs/tile unchanged.
// smem: Ks 64x68 + Vt 64x68 = 34816 B.
// ---------------------------------------------------------------------------
constexpr int SK = 68;

__global__ __launch_bounds__(256, 2) void attn_tc_kernel()
{
    __shared__ float Ks[64 * SK];  // K[key][d]
    __shared__ float Vt[64 * SK];  // V^T[d][key]

    const int tid = threadIdx.x;
    const int w = tid >> 5;
    const int lane = tid & 31;
    const int g = lane >> 2;
    const int t = lane & 3;

    const int bh = blockIdx.y;
    const int q0 = blockIdx.x * 128;
    const int qlo = q0 + w * 16 + g;

    const float* qb = g_q + (size_t)bh * N_ * D_;
    const float* kb = g_k + (size_t)bh * N_ * D_;
    const float* vb = g_v + (size_t)bh * N_ * D_;

    // Q A-fragments, pre-scaled, register-resident (R4 numerics).
    unsigned qf[8][4];
#pragma unroll
    for (int s = 0; s < 8; s++) {
        const float* plo = qb + (size_t)qlo * D_ + s * 8 + t;
        const float* phi = plo + 8 * D_;
        qf[s][0] = __float_as_uint(plo[0] * SCALE);
        qf[s][1] = __float_as_uint(phi[0] * SCALE);
        qf[s][2] = __float_as_uint(plo[4] * SCALE);
        qf[s][3] = __float_as_uint(phi[4] * SCALE);
    }

    float oacc[8][4];
#pragma unroll
    for (int j = 0; j < 8; j++)
#pragma unroll
        for (int q = 0; q < 4; q++) oacc[j][q] = 0.f;
    float m_lo = -CUDART_INF_F, m_hi = -CUDART_INF_F;
    float l_lo = 0.f, l_hi = 0.f;

    const int r0 = tid >> 2;             // 0..63 (key row for staging)
    const int c4 = (tid & 3) * 4;        // d base
    const int src_lo = (lane & 28) | (t >> 1);
    const int src_hi = src_lo + 2;
    const bool odd = t & 1;

    // ---- prologue: load tile 0 into regs; STS K[0] (visible at first syncA)
    float4 kv[4], vv[4];
#pragma unroll
    for (int ch = 0; ch < 4; ch++) {
        const int d = c4 + ch * 16;
        kv[ch] = *(const float4*)(kb + (size_t)r0 * D_ + d);
        vv[ch] = *(const float4*)(vb + (size_t)r0 * D_ + d);
    }
#pragma unroll
    for (int ch = 0; ch < 4; ch++) {
        const int d = c4 + ch * 16;
        *(float4*)&Ks[r0 * SK + d] = kv[ch];
    }

    for (int it = 0; it < 32; it++) {
        __syncthreads();   // syncA: Ks[it] visible; Vt[it-1] readers done

        // STS V[it] from regs loaded last iteration (latency long gone)
#pragma unroll
        for (int ch = 0; ch < 4; ch++) {
            const int d = c4 + ch * 16;
            Vt[(d + 0) * SK + r0] = vv[ch].x;
            Vt[(d + 1) * SK + r0] = vv[ch].y;
            Vt[(d + 2) * SK + r0] = vv[ch].z;
            Vt[(d + 3) * SK + r0] = vv[ch].w;
        }

        // LDG tile it+1 into regs — consumed after syncB / next syncA
        if (it < 31) {
            const size_t base = ((size_t)(it + 1) * 64 + r0) * D_;
#pragma unroll
            for (int ch = 0; ch < 4; ch++) {
                const int d = c4 + ch * 16;
                kv[ch] = *(const float4*)(kb + base + d);
                vv[ch] = *(const float4*)(vb + base + d);
            }
        }

        // S = Q @ K^T (R4-identical reads)
        float sacc[8][4];
#pragma unroll
        for (int j = 0; j < 8; j++)
#pragma unroll
            for (int q = 0; q < 4; q++) sacc[j][q] = 0.f;
#pragma unroll
        for (int s = 0; s < 8; s++) {
#pragma unroll
            for (int j = 0; j < 8; j++) {
                const float* p = &Ks[(j * 8 + g) * SK + s * 8 + t];
                mma_tf32(sacc[j][0], sacc[j][1], sacc[j][2], sacc[j][3],
                         qf[s][0], qf[s][1], qf[s][2], qf[s][3],
                         __float_as_uint(p[0]), __float_as_uint(p[4]));
            }
        }

        // Online softmax (R4-identical)
        float mx_lo = -CUDART_INF_F, mx_hi = -CUDART_INF_F;
#pragma unroll
        for (int j = 0; j < 8; j++) {
            mx_lo = fmaxf(mx_lo, fmaxf(sacc[j][0], sacc[j][1]));
            mx_hi = fmaxf(mx_hi, fmaxf(sacc[j][2], sacc[j][3]));
        }
#pragma unroll
        for (int off = 2; off >= 1; off >>= 1) {
            mx_lo = fmaxf(mx_lo, __shfl_xor_sync(0xffffffffu, mx_lo, off));
            mx_hi = fmaxf(mx_hi, __shfl_xor_sync(0xffffffffu, mx_hi, off));
        }
        const float mn_lo = fmaxf(m_lo, mx_lo);
        const float mn_hi = fmaxf(m_hi, mx_hi);
        const float al_lo = __expf(m_lo - mn_lo);
        const float al_hi = __expf(m_hi - mn_hi);
        float rs_lo = 0.f, rs_hi = 0.f;
#pragma unroll
        for (int j = 0; j < 8; j++) {
            sacc[j][0] = __expf(sacc[j][0] - mn_lo);
            sacc[j][1] = __expf(sacc[j][1] - mn_lo);
            sacc[j][2] = __expf(sacc[j][2] - mn_hi);
            sacc[j][3] = __expf(sacc[j][3] - mn_hi);
            rs_lo += sacc[j][0] + sacc[j][1];
            rs_hi += sacc[j][2] + sacc[j][3];
        }
#pragma unroll
        for (int off = 2; off >= 1; off >>= 1) {
            rs_lo += __shfl_xor_sync(0xffffffffu, rs_lo, off);
            rs_hi += __shfl_xor_sync(0xffffffffu, rs_hi, off);
        }
        l_lo = l_lo * al_lo + rs_lo;  m_lo = mn_lo;
        l_hi = l_hi * al_hi + rs_hi;  m_hi = mn_hi;
#pragma unroll
        for (int j = 0; j < 8; j++) {
            oacc[j][0] *= al_lo; oacc[j][1] *= al_lo;
            oacc[j][2] *= al_hi; oacc[j][3] *= al_hi;
        }

        __syncthreads();   // syncB: Vt[it] visible; Ks readers done

        // STS K[it+1] (regs from top of this iteration; visible at next syncA)
        if (it < 31) {
#pragma unroll
            for (int ch = 0; ch < 4; ch++) {
                const int d = c4 + ch * 16;
                *(float4*)&Ks[r0 * SK + d] = kv[ch];
            }
        }

        // O += P @ V (R4-identical reads)
#pragma unroll
        for (int s = 0; s < 8; s++) {
            const float x0 = __shfl_sync(0xffffffffu, sacc[s][0], src_lo);
            const float x1 = __shfl_sync(0xffffffffu, sacc[s][1], src_lo);
            const float x2 = __shfl_sync(0xffffffffu, sacc[s][2], src_lo);
            const float x3 = __shfl_sync(0xffffffffu, sacc[s][3], src_lo);
            const float y0 = __shfl_sync(0xffffffffu, sacc[s][0], src_hi);
            const float y1 = __shfl_sync(0xffffffffu, sacc[s][1], src_hi);
            const float y2 = __shfl_sync(0xffffffffu, sacc[s][2], src_hi);
            const float y3 = __shfl_sync(0xffffffffu, sacc[s][3], src_hi);
            const unsigned a0 = f2tf(odd ? x1 : x0);
            const unsigned a1 = f2tf(odd ? x3 : x2);
            const unsigned a2 = f2tf(odd ? y1 : y0);
            const unsigned a3 = f2tf(odd ? y3 : y2);
#pragma unroll
            for (int jd = 0; jd < 8; jd++) {
                const float* p = &Vt[(jd * 8 + g) * SK + s * 8 + t];
                mma_tf32(oacc[jd][0], oacc[jd][1], oacc[jd][2], oacc[jd][3],
                         a0, a1, a2, a3,
                         __float_as_uint(p[0]), __float_as_uint(p[4]));
            }
        }
    }

    // Normalize and write to g_ao [B*N, C]
    const float inv_lo = 1.0f / l_lo;
    const float inv_hi = 1.0f / l_hi;
    const int b = bh >> 4;
    const int h = bh & (H_ - 1);
#pragma unroll
    for (int jd = 0; jd < 8; jd++) {
        const int col = h * D_ + jd * 8 + 2 * t;
        float2 o0 = {oacc[jd][0] * inv_lo, oacc[jd][1] * inv_lo};
        float2 o1 = {oacc[jd][2] * inv_hi, oacc[jd][3] * inv_hi};
        *(float2*)&g_ao[((size_t)(b * N_ + qlo)) * C_ + col] = o0;
        *(float2*)&g_ao[((size_t)(b * N_ + qlo + 8)) * C_ + col] = o1;
    }
}

// ---------------------------------------------------------------------------
extern "C" void kernel_launch(void* const* d_in, const int* in_sizes, int n_in,
                              void* d_out, int out_size)
{
    (void)in_sizes; (void)n_in; (void)out_size;
    const float* x      = (const float*)d_in[0];
    const float* qkv_w  = (const float*)d_in[1];
    const float* proj_w = (const float*)d_in[2];
    const float* proj_b = (const float*)d_in[3];
    const float* fcos   = (const float*)d_in[4];
    const float* fsin   = (const float*)d_in[5];
    float* out = (float*)d_out;

    // 1) QKV GEMM (R4-exact tf32) + RoPE scatter
    gemm_tf32_kernel<0><<<dim3(3 * C_ / 128, M_ / 128), 256>>>(
        x, qkv_w, fcos, fsin, nullptr, nullptr);
    // 2) Flash attention (R4 math, rescheduled latency-free staging)
    attn_tc_kernel<<<dim3(N_ / 128, B_ * H_), 256>>>();
    // 3) Output projection (R4-exact tf32) + bias
    gemm_tf32_kernel<1><<<dim3(C_ / 128, M_ / 128), 256>>>(
        nullptr, proj_w, nullptr, nullptr, proj_b, out);
}